// round 14
// baseline (speedup 1.0000x reference)
#include <cuda_runtime.h>
#include <math.h>
#include <stdint.h>

// Problem constants
#define BQ   16
#define CDIM 256
#define HW   64
#define NQ   65536
#define KCODES 1024
#define ZQ_ELEMS 16777216

#define MARGIN 1e-3f
#define CAND_CAP 8

// GEMM tiling
#define MT   128
#define NTC  128
#define KT   16
#define NCHUNKS 8
#define KTILES  16
#define NTILES  (NCHUNKS * KTILES)       // 128

typedef unsigned long long u64;

// Dynamic smem (bytes) for GEMM: A dup'd [3][16][256]f, B [3][16][128]f
#define SMA_OFF   0                       // 3 * 16384 = 49152
#define SMB_OFF   49152                   // 3 * 8192  = 24576
#define SBV_OFF   73728
#define SBI_OFF   (SBV_OFF + 512)
#define SCNT_OFF  (SBI_OFF + 512)
#define SCAND_OFF (SCNT_OFF + 512)
#define SM_TOTAL  (SCAND_OFF + MT * CAND_CAP * 4)   // 79360

// Scratch
__device__ float  g_zfA[(size_t)CDIM * 2 * NQ];  // [C][2N] DUPLICATED queries (GEMM A + refine)
__device__ float  g_wn [KCODES * CDIM];          // [K][C] (refine)
__device__ float  g_wnT[CDIM * KCODES];          // [C][K] (GEMM B)
__device__ float  g_wn2[KCODES];
__device__ float  g_en [KCODES];
__device__ float  g_en2[KCODES];
__device__ int    g_bi[NQ];
__device__ float  g_bd[NQ];
__device__ int    g_ncand[NQ];
__device__ int    g_cand[NQ * CAND_CAP];
__device__ double g_loss;

// ---- helpers ----
__device__ __forceinline__ uint32_t smem_u32(const void* p) {
    uint32_t a;
    asm("{ .reg .u64 t; cvta.to.shared.u64 t, %1; cvt.u32.u64 %0, t; }" : "=r"(a) : "l"(p));
    return a;
}
__device__ __forceinline__ void ffma2(u64& d, u64 a, u64 b) {
    asm("fma.rn.f32x2 %0, %1, %2, %0;" : "+l"(d) : "l"(a), "l"(b));
}
__device__ __forceinline__ float2 unpk(u64 v) {
    float2 f; asm("mov.b64 {%0, %1}, %2;" : "=f"(f.x), "=f"(f.y) : "l"(v)); return f;
}
__device__ __forceinline__ void cpasync16(uint32_t dst, const void* src) {
    asm volatile("cp.async.cg.shared.global [%0], [%1], 16;" :: "r"(dst), "l"(src));
}
#define CP_COMMIT() asm volatile("cp.async.commit_group;" ::: "memory")
#define CP_WAIT_1() asm volatile("cp.async.wait_group 1;" ::: "memory")
#define CP_WAIT_0() asm volatile("cp.async.wait_group 0;" ::: "memory")

// Markstein correctly-rounded fp32 division (bit-equal to '/')
__device__ __forceinline__ float div_rn(float x, float d, float r) {
    float q = x * r;
    return fmaf(fmaf(-q, d, x), r, q);
}

// ---------------------------------------------------------------------------
// Kernel 1: normalize embedding rows (ref-emulating), norms, transposed copy
// ---------------------------------------------------------------------------
__global__ void k_prep(const float* __restrict__ emb) {
    int k = blockIdx.x, t = threadIdx.x;
    if (k == 0 && t == 0) g_loss = 0.0;

    __shared__ double red[256];
    float v = emb[k * CDIM + t];
    red[t] = (double)v * (double)v;
    __syncthreads();
    #pragma unroll
    for (int s = 128; s > 0; s >>= 1) { if (t < s) red[t] += red[t + s]; __syncthreads(); }
    __shared__ float sDen;
    if (t == 0) {
        float n2 = (float)red[0];
        float n  = sqrtf(n2);
        float dd = fmaxf(n, 1e-12f);
        g_en[k] = dd; g_en2[k] = n2; sDen = dd;
    }
    __syncthreads();
    float wn = v / sDen;
    g_wn [k * CDIM + t]   = wn;
    g_wnT[t * KCODES + k] = wn;

    red[t] = (double)wn * (double)wn;
    __syncthreads();
    #pragma unroll
    for (int s = 128; s > 0; s >>= 1) { if (t < s) red[t] += red[t + s]; __syncthreads(); }
    if (t == 0) g_wn2[k] = (float)red[0];
}

// ---------------------------------------------------------------------------
// Kernel 2: znorm, warp-per-row. Row = 64 contiguous W floats of z[b,c,h,:].
// fp64 sumsq (shfl), ONE division per row (lane0 + bcast), Markstein per elem
// (bit-equal to '/'), duplicated float2 writes into g_zfA[c][2n].
// ---------------------------------------------------------------------------
__global__ void k_znorm(const float* __restrict__ z) {
    const int lane = threadIdx.x & 31;
    const int nwarps = (gridDim.x * blockDim.x) >> 5;
    int wid = (blockIdx.x * blockDim.x + threadIdx.x) >> 5;

    for (int row = wid; row < BQ * CDIM * HW; row += nwarps) {
        // row = (b*256 + c)*64 + h  (z row index)
        const float* src = z + (size_t)row * 64;
        float v0 = src[lane];
        float v1 = src[lane + 32];
        double s = (double)v0 * v0 + (double)v1 * v1;
        #pragma unroll
        for (int off = 16; off > 0; off >>= 1)
            s += __shfl_xor_sync(0xFFFFFFFFu, s, off);
        float den = fmaxf(sqrtf((float)s), 1e-12f);
        float r0 = 0.0f;
        if (lane == 0) r0 = 1.0f / den;            // one true div per row
        float r = __shfl_sync(0xFFFFFFFFu, r0, 0);
        float q0 = div_rn(v0, den, r);
        float q1 = div_rn(v1, den, r);

        int b = row >> 14;
        int c = (row >> 6) & 255;
        int h = row & 63;
        size_t n0 = ((size_t)b * 64 + h) * 64;     // query base for this (b,h)
        float2* dst = (float2*)(g_zfA + (size_t)c * (2 * (size_t)NQ));
        dst[n0 + lane]      = make_float2(q0, q0);
        dst[n0 + 32 + lane] = make_float2(q1, q1);
    }
}

// ---------------------------------------------------------------------------
// Marker: keeps ncu's capture window (4th launch) on the GEMM
// ---------------------------------------------------------------------------
__global__ void k_marker() { if (threadIdx.x == 1024) g_loss = -1.0; }

// ---------------------------------------------------------------------------
// Kernel 3: fp32x2 GEMM screen, A pre-duplicated in gmem -> zero dup-MOVs.
// 512 CTAs x 256 threads, 2 CTAs/SM, 3-stage cp.async on A and B.
// Per kk: 6 wide LDS + 32 FFMA2, all operands direct LDS reinterprets.
// ---------------------------------------------------------------------------
__global__ void __launch_bounds__(256, 2) k_gemm_argmax() {
    extern __shared__ float smem[];
    float* s_bv   = smem + SBV_OFF / 4;
    int*   s_bi   = (int*)(smem + SBI_OFF / 4);
    int*   s_cnt  = (int*)(smem + SCNT_OFF / 4);
    int*   s_cand = (int*)(smem + SCAND_OFF / 4);

    const int t  = threadIdx.x;
    const int tx = t & 15;
    const int ty = t >> 4;
    const int n0 = blockIdx.x * MT;

    if (t < MT) { s_bv[t] = -3.0e38f; s_bi[t] = 0; s_cnt[t] = 0; }

    const uint32_t smb = smem_u32(smem);
    // A loader coords: 1024 x 16B per tile -> 4/thread
    const int arow = t >> 6;                 // 0..3 (+4i)
    const int acol = (t & 63);               // x16B
    // B loader coords: 512 x 16B per tile -> 2/thread
    const int brow = t >> 5;                 // 0..7 (+8i)
    const int bcol = (t & 31);               // x16B

    #define KICK_TILE(bt_) do {                                                    \
        const int ch_ = (bt_) >> 4, kt_ = (bt_) & 15;                              \
        const int buf_ = (bt_) % 3;                                                \
        const uint32_t ab = smb + (uint32_t)(SMA_OFF + buf_ * 16384);              \
        const uint32_t bb = smb + (uint32_t)(SMB_OFF + buf_ * 8192);               \
        _Pragma("unroll")                                                          \
        for (int i_ = 0; i_ < 4; i_++) {                                           \
            int r_ = arow + i_ * 4;                                                \
            cpasync16(ab + (uint32_t)(r_ * 1024 + acol * 16),                      \
                      g_zfA + (size_t)(kt_ * KT + r_) * (2 * (size_t)NQ)           \
                            + 2 * (size_t)n0 + acol * 4);                          \
        }                                                                          \
        _Pragma("unroll")                                                          \
        for (int i_ = 0; i_ < 2; i_++) {                                           \
            int r_ = brow + i_ * 8;                                                \
            cpasync16(bb + (uint32_t)(r_ * 512 + bcol * 16),                       \
                      g_wnT + (size_t)(kt_ * KT + r_) * KCODES + ch_ * NTC         \
                            + bcol * 4);                                           \
        }                                                                          \
    } while (0)

    KICK_TILE(0); CP_COMMIT();
    KICK_TILE(1); CP_COMMIT();

    u64 acc[8][4];

    for (int bt = 0; bt < NTILES; bt++) {
        CP_WAIT_1();
        __syncthreads();

        if (bt + 2 < NTILES) { KICK_TILE(bt + 2); }
        CP_COMMIT();

        const int kt  = bt & 15;
        const int buf = bt % 3;
        const float* Ab = smem + (SMA_OFF / 4) + buf * 4096;
        const float* Bb = smem + (SMB_OFF / 4) + buf * 2048;

        if (kt == 0) {
            #pragma unroll
            for (int i = 0; i < 8; i++)
                #pragma unroll
                for (int j = 0; j < 4; j++) acc[i][j] = 0ull;
        }

        #pragma unroll
        for (int kk = 0; kk < KT; kk++) {
            const u64* Ak64 = (const u64*)(Ab + kk * 256 + ty * 16);  // 8 dup'd pairs
            const u64* Bk64 = (const u64*)(Bb + kk * 128 + tx * 8);   // 4 natural pairs
            u64 b2[4];
            #pragma unroll
            for (int j = 0; j < 4; j++) b2[j] = Bk64[j];
            u64 a2[8];
            #pragma unroll
            for (int i = 0; i < 8; i++) a2[i] = Ak64[i];
            #pragma unroll
            for (int i = 0; i < 8; i++)
                #pragma unroll
                for (int j = 0; j < 4; j++)
                    ffma2(acc[i][j], a2[i], b2[j]);
        }

        if (kt == 15) {
            const int code0 = (bt >> 4) * NTC;
            #pragma unroll
            for (int i = 0; i < 8; i++) {
                float bv = -3.0e38f;
                int   bj = 0;
                #pragma unroll
                for (int j = 0; j < 4; j++) {
                    float2 p = unpk(acc[i][j]);
                    if (p.x > bv) { bv = p.x; bj = 2 * j; }
                    if (p.y > bv) { bv = p.y; bj = 2 * j + 1; }
                }
                int bc = code0 + tx * 8 + bj;
                #pragma unroll
                for (int off = 8; off > 0; off >>= 1) {
                    float ov = __shfl_xor_sync(0xFFFFFFFFu, bv, off, 16);
                    int   oc = __shfl_xor_sync(0xFFFFFFFFu, bc, off, 16);
                    if (ov > bv || (ov == bv && oc < bc)) { bv = ov; bc = oc; }
                }
                if (tx == 0) {
                    int row = ty * 8 + i;
                    if (bv > s_bv[row]) { s_bv[row] = bv; s_bi[row] = bc; }
                }
            }
            #pragma unroll
            for (int i = 0; i < 8; i++) {
                int row = ty * 8 + i;
                float thr = s_bv[row] - MARGIN;
                #pragma unroll
                for (int j = 0; j < 4; j++) {
                    float2 p = unpk(acc[i][j]);
                    if (p.x >= thr) {
                        int pos = atomicAdd(&s_cnt[row], 1);
                        if (pos < CAND_CAP) s_cand[row * CAND_CAP + pos] = code0 + tx * 8 + 2 * j;
                    }
                    if (p.y >= thr) {
                        int pos = atomicAdd(&s_cnt[row], 1);
                        if (pos < CAND_CAP) s_cand[row * CAND_CAP + pos] = code0 + tx * 8 + 2 * j + 1;
                    }
                }
            }
        }
    }

    __syncthreads();
    if (t < MT) {
        int n = n0 + t;
        g_bi[n] = s_bi[t];
        g_bd[n] = s_bv[t];
        int cnt = s_cnt[t];
        g_ncand[n] = cnt;
        int m = cnt < CAND_CAP ? cnt : CAND_CAP;
        for (int c = 0; c < m; c++) g_cand[n * CAND_CAP + c] = s_cand[t * CAND_CAP + c];
    }
    CP_WAIT_0();
    #undef KICK_TILE
}

// ---------------------------------------------------------------------------
// Kernel 4: exact re-ranking (fp64). Query vec read strided from g_zfA.
// ---------------------------------------------------------------------------
__global__ void k_refine(float* __restrict__ out_idx) {
    int warp = (blockIdx.x * blockDim.x + threadIdx.x) >> 5;
    int lane = threadIdx.x & 31;
    __shared__ double s_loss;
    if (threadIdx.x == 0) s_loss = 0.0;
    __syncthreads();

    if (warp < NQ) {
        int n = warp;
        int cnt = g_ncand[n];
        int bi; float bd;
        if (cnt <= 1) {
            bi = g_bi[n]; bd = g_bd[n];
        } else {
            float zr[8];
            #pragma unroll
            for (int m = 0; m < 8; m++)
                zr[m] = g_zfA[(size_t)(lane + 32 * m) * (2 * (size_t)NQ) + 2 * (size_t)n];
            double z2 = 0.0;
            #pragma unroll
            for (int m = 0; m < 8; m++) z2 += (double)zr[m] * (double)zr[m];
            #pragma unroll
            for (int off = 16; off > 0; off >>= 1)
                z2 += __shfl_xor_sync(0xFFFFFFFFu, z2, off);
            float zf2f = (float)z2;

            bool overflow = (cnt > CAND_CAP);
            int ncand = overflow ? KCODES : cnt;
            float dmin = 3.4e38f; int kmin = 0x7FFFFFFF; float bestdot = 0.0f;
            for (int ci = 0; ci < ncand; ci++) {
                int k = overflow ? ci : g_cand[n * CAND_CAP + ci];
                double dot = 0.0;
                const float* wrow = g_wn + (size_t)k * CDIM;
                #pragma unroll
                for (int m = 0; m < 8; m++)
                    dot += (double)zr[m] * (double)wrow[lane + 32 * m];
                #pragma unroll
                for (int off = 16; off > 0; off >>= 1)
                    dot += __shfl_xor_sync(0xFFFFFFFFu, dot, off);
                float dotf = (float)dot;
                float d = (zf2f + g_wn2[k]) - 2.0f * dotf;
                if (d < dmin || (d == dmin && k < kmin)) { dmin = d; kmin = k; bestdot = dotf; }
            }
            bi = kmin; bd = bestdot;
        }
        if (lane == 0) {
            g_bi[n] = bi;
            out_idx[n] = (float)bi;
            atomicAdd(&s_loss, (double)g_en2[bi] - 2.0 * (double)bd * (double)g_en[bi]);
        }
    }
    __syncthreads();
    if (threadIdx.x == 0) atomicAdd(&g_loss, s_loss);
}

// ---------------------------------------------------------------------------
// Kernel 5: direct gather: out[b,c,h,w] = emb[bi[n]*256 + c]
// ---------------------------------------------------------------------------
__global__ void k_gather(const float* __restrict__ emb, float* __restrict__ out) {
    int tid = blockIdx.x * blockDim.x + threadIdx.x;
    const int stride = gridDim.x * blockDim.x;
    #pragma unroll 4
    for (int idx = tid; idx < ZQ_ELEMS; idx += stride) {
        int w = idx & 63;
        int h = (idx >> 6) & 63;
        int c = (idx >> 12) & 255;
        int b = idx >> 20;
        int n = (b << 12) | (h << 6) | w;
        out[idx] = __ldg(&emb[(size_t)g_bi[n] * CDIM + c]);
    }
}

// ---------------------------------------------------------------------------
// Kernel 6: finalize loss. Sum_n ||zf_n||^2 == 262144 exactly.
// ---------------------------------------------------------------------------
__global__ void k_loss(float* __restrict__ out_loss) {
    double S = g_loss + 262144.0;
    out_loss[0] = (float)(1.25 * S / (double)ZQ_ELEMS);
}

// ---------------------------------------------------------------------------
extern "C" void kernel_launch(void* const* d_in, const int* in_sizes, int n_in,
                              void* d_out, int out_size) {
    const float* z   = (const float*)d_in[0];
    const float* emb = (const float*)d_in[1];
    float* out = (float*)d_out;

    cudaFuncSetAttribute(k_gemm_argmax, cudaFuncAttributeMaxDynamicSharedMemorySize, SM_TOTAL);

    k_prep<<<KCODES, 256>>>(emb);                      // 1
    k_znorm<<<1024, 256>>>(z);                         // 2
    k_marker<<<1, 32>>>();                             // 3
    k_gemm_argmax<<<NQ / MT, 256, SM_TOTAL>>>();       // 4  <- profiled
    k_refine<<<NQ / 8, 256>>>(out + ZQ_ELEMS);         // 5
    k_gather<<<2048, 256>>>(emb, out);                 // 6
    k_loss<<<1, 1>>>(out + ZQ_ELEMS + NQ);             // 7
}

// round 15
// speedup vs baseline: 1.1147x; 1.1147x over previous
#include <cuda_runtime.h>
#include <math.h>
#include <stdint.h>

// Problem constants
#define BQ   16
#define CDIM 256
#define HW   64
#define NQ   65536
#define KCODES 1024
#define ZQ_ELEMS 16777216

#define MARGIN 1e-3f
#define CAND_CAP 8

// GEMM tiling
#define MT   128
#define NTC  128
#define KT   32        // k per tile (doubled: half the barriers)
#define NCHUNKS 8
#define KTILES  8                        // per chunk (256/32)
#define NTILES  (NCHUNKS * KTILES)       // 64

typedef unsigned long long u64;

// Dynamic smem (bytes): A[3][32][128]f, B[3][32][128]f, epilogue arrays
#define SMA_OFF   0                      // 3 * 16384 = 49152
#define SMB_OFF   49152                  // 3 * 16384 = 49152
#define SBV_OFF   98304
#define SBI_OFF   (SBV_OFF + 512)
#define SCNT_OFF  (SBI_OFF + 512)
#define SCAND_OFF (SCNT_OFF + 512)
#define SM_TOTAL  (SCAND_OFF + MT * CAND_CAP * 4)   // 103936

// Scratch
__device__ float  g_zf [NQ * CDIM];      // [N][C] (refine)
__device__ float  g_zfT[CDIM * NQ];      // [C][N] (GEMM A)
__device__ float  g_wn [KCODES * CDIM];  // [K][C] (refine)
__device__ float  g_wnT[CDIM * KCODES];  // [C][K] (GEMM B)
__device__ float  g_wn2[KCODES];
__device__ float  g_en [KCODES];
__device__ float  g_en2[KCODES];
__device__ int    g_bi[NQ];
__device__ float  g_bd[NQ];
__device__ int    g_ncand[NQ];
__device__ int    g_cand[NQ * CAND_CAP];
__device__ double g_loss;

// ---- helpers ----
__device__ __forceinline__ uint32_t smem_u32(const void* p) {
    uint32_t a;
    asm("{ .reg .u64 t; cvta.to.shared.u64 t, %1; cvt.u32.u64 %0, t; }" : "=r"(a) : "l"(p));
    return a;
}
__device__ __forceinline__ u64 pack_dup(float a) {
    u64 r; asm("mov.b64 %0, {%1, %1};" : "=l"(r) : "f"(a)); return r;
}
__device__ __forceinline__ void ffma2(u64& d, u64 a, u64 b) {
    asm("fma.rn.f32x2 %0, %1, %2, %0;" : "+l"(d) : "l"(a), "l"(b));
}
__device__ __forceinline__ float2 unpk(u64 v) {
    float2 f; asm("mov.b64 {%0, %1}, %2;" : "=f"(f.x), "=f"(f.y) : "l"(v)); return f;
}
__device__ __forceinline__ void cpasync16(uint32_t dst, const void* src) {
    asm volatile("cp.async.cg.shared.global [%0], [%1], 16;" :: "r"(dst), "l"(src));
}
#define CP_COMMIT() asm volatile("cp.async.commit_group;" ::: "memory")
#define CP_WAIT_1() asm volatile("cp.async.wait_group 1;" ::: "memory")
#define CP_WAIT_0() asm volatile("cp.async.wait_group 0;" ::: "memory")

// Markstein correctly-rounded fp32 division (bit-equal to '/')
__device__ __forceinline__ float div_rn(float x, float d, float r) {
    float q = x * r;
    return fmaf(fmaf(-q, d, x), r, q);
}

// ---------------------------------------------------------------------------
// Kernel 1: fused prep (blocks 1024..2047) + znorm (blocks 0..1023)
// (proven: ~101us profiled)
// ---------------------------------------------------------------------------
__global__ void k_prepnorm(const float* __restrict__ z, const float* __restrict__ emb) {
    __shared__ float tile[64][65];
    __shared__ float den[64];
    __shared__ float rcp[64];
    __shared__ double red[256];

    const int t = threadIdx.x;

    if (blockIdx.x >= 1024) {
        int k = blockIdx.x - 1024;
        if (k == 0 && t == 0) g_loss = 0.0;

        float v = emb[k * CDIM + t];
        red[t] = (double)v * (double)v;
        __syncthreads();
        #pragma unroll
        for (int s = 128; s > 0; s >>= 1) { if (t < s) red[t] += red[t + s]; __syncthreads(); }
        __shared__ float sDen;
        if (t == 0) {
            float n2 = (float)red[0];
            float n  = sqrtf(n2);
            float dd = fmaxf(n, 1e-12f);
            g_en[k] = dd; g_en2[k] = n2; sDen = dd;
        }
        __syncthreads();
        float wn = v / sDen;
        g_wn [k * CDIM + t]   = wn;
        g_wnT[t * KCODES + k] = wn;

        red[t] = (double)wn * (double)wn;
        __syncthreads();
        #pragma unroll
        for (int s = 128; s > 0; s >>= 1) { if (t < s) red[t] += red[t + s]; __syncthreads(); }
        if (t == 0) g_wn2[k] = (float)red[0];
        return;
    }

    int bh = blockIdx.x;
    int b = bh >> 6, h = bh & 63;
    long n0 = (long)bh * 64;

    for (int c0 = 0; c0 < CDIM; c0 += 64) {
        for (int i = t; i < 4096; i += 256) {
            int r = i >> 6, w = i & 63;
            tile[r][w] = z[(((long)b * CDIM + (c0 + r)) * HW + h) * HW + w];
        }
        __syncthreads();
        if (t < 64) {
            double s = 0.0;
            #pragma unroll
            for (int w = 0; w < 64; w++) { double v = (double)tile[t][w]; s += v * v; }
            float d = fmaxf(sqrtf((float)s), 1e-12f);
            den[t] = d;
            rcp[t] = 1.0f / d;
        }
        __syncthreads();
        for (int i = t; i < 4096; i += 256) {
            int r = i >> 6, w = i & 63;
            tile[r][w] = div_rn(tile[r][w], den[r], rcp[r]);
        }
        __syncthreads();
        for (int i = t; i < 4096; i += 256) {
            int w = i >> 6, cc = i & 63;
            g_zf[(n0 + w) * CDIM + c0 + cc] = tile[cc][w];
        }
        for (int i = t; i < 4096; i += 256) {
            int cc = i >> 6, w = i & 63;
            g_zfT[(long)(c0 + cc) * NQ + n0 + w] = tile[cc][w];
        }
        __syncthreads();
    }
}

// ---------------------------------------------------------------------------
// Markers: keep ncu's capture window (4th launch) on the GEMM
// ---------------------------------------------------------------------------
__global__ void k_marker() { if (threadIdx.x == 1024) g_loss = -1.0; }

// ---------------------------------------------------------------------------
// Kernel 2: fp32x2 GEMM screen, KT=32 (64 barriers instead of 128),
// 2 CTAs/SM, 3-stage cp.async on A AND B. Inner loop identical to R9.
// ---------------------------------------------------------------------------
__global__ void __launch_bounds__(256, 2) k_gemm_argmax() {
    extern __shared__ float smem[];
    float* s_bv   = smem + SBV_OFF / 4;
    int*   s_bi   = (int*)(smem + SBI_OFF / 4);
    int*   s_cnt  = (int*)(smem + SCNT_OFF / 4);
    int*   s_cand = (int*)(smem + SCAND_OFF / 4);

    const int t  = threadIdx.x;
    const int tx = t & 15;
    const int ty = t >> 4;
    const int n0 = blockIdx.x * MT;

    if (t < MT) { s_bv[t] = -3.0e38f; s_bi[t] = 0; s_cnt[t] = 0; }

    const uint32_t smb = smem_u32(smem);
    // loader coords: 1024 float4 per (A or B) tile, 4 per thread
    const int lr = t >> 5;                 // 0..7 (+8i)
    const int lc = (t & 31) * 16;          // byte offset within 512B row

    #define KICK_TILE(bt_) do {                                                   \
        const int ch_ = (bt_) >> 3, kt_ = (bt_) & 7;                              \
        const int buf_ = (bt_) % 3;                                               \
        const uint32_t ab = smb + (uint32_t)(SMA_OFF + buf_ * 16384);             \
        const uint32_t bb = smb + (uint32_t)(SMB_OFF + buf_ * 16384);             \
        _Pragma("unroll")                                                         \
        for (int i_ = 0; i_ < 4; i_++) {                                          \
            int r_ = lr + i_ * 8;                                                 \
            cpasync16(ab + (uint32_t)(r_ * 512 + lc),                             \
                      g_zfT + (size_t)(kt_ * KT + r_) * NQ + n0 + (lc >> 2));     \
            cpasync16(bb + (uint32_t)(r_ * 512 + lc),                             \
                      g_wnT + (size_t)(kt_ * KT + r_) * KCODES + ch_ * NTC        \
                            + (lc >> 2));                                         \
        }                                                                         \
    } while (0)

    KICK_TILE(0); CP_COMMIT();
    KICK_TILE(1); CP_COMMIT();

    u64 acc[8][4];

    for (int bt = 0; bt < NTILES; bt++) {
        CP_WAIT_1();
        __syncthreads();

        if (bt + 2 < NTILES) { KICK_TILE(bt + 2); }
        CP_COMMIT();

        const int kt  = bt & 7;
        const int buf = bt % 3;
        const float* Ab = smem + (SMA_OFF / 4) + buf * 4096;
        const float* Bb = smem + (SMB_OFF / 4) + buf * 4096;

        if (kt == 0) {
            #pragma unroll
            for (int i = 0; i < 8; i++)
                #pragma unroll
                for (int j = 0; j < 4; j++) acc[i][j] = 0ull;
        }

        #pragma unroll
        for (int kk = 0; kk < KT; kk++) {
            const float* Ak = Ab + kk * MT;
            const float* Bk = Bb + kk * NTC;
            u64 b2[4];
            #pragma unroll
            for (int j = 0; j < 4; j++)
                b2[j] = *(const u64*)(Bk + tx * 8 + 2 * j);
            float4 av0 = *(const float4*)(Ak + ty * 8);
            float4 av1 = *(const float4*)(Ak + ty * 8 + 4);
            float av[8] = {av0.x, av0.y, av0.z, av0.w, av1.x, av1.y, av1.z, av1.w};
            #pragma unroll
            for (int i = 0; i < 8; i++) {
                u64 a2 = pack_dup(av[i]);
                #pragma unroll
                for (int j = 0; j < 4; j++)
                    ffma2(acc[i][j], a2, b2[j]);
            }
        }

        if (kt == 7) {
            const int code0 = (bt >> 3) * NTC;
            #pragma unroll
            for (int i = 0; i < 8; i++) {
                float bv = -3.0e38f;
                int   bj = 0;
                #pragma unroll
                for (int j = 0; j < 4; j++) {
                    float2 p = unpk(acc[i][j]);
                    if (p.x > bv) { bv = p.x; bj = 2 * j; }
                    if (p.y > bv) { bv = p.y; bj = 2 * j + 1; }
                }
                int bc = code0 + tx * 8 + bj;
                #pragma unroll
                for (int off = 8; off > 0; off >>= 1) {
                    float ov = __shfl_xor_sync(0xFFFFFFFFu, bv, off, 16);
                    int   oc = __shfl_xor_sync(0xFFFFFFFFu, bc, off, 16);
                    if (ov > bv || (ov == bv && oc < bc)) { bv = ov; bc = oc; }
                }
                if (tx == 0) {
                    int row = ty * 8 + i;
                    if (bv > s_bv[row]) { s_bv[row] = bv; s_bi[row] = bc; }
                }
            }
            #pragma unroll
            for (int i = 0; i < 8; i++) {
                int row = ty * 8 + i;
                float thr = s_bv[row] - MARGIN;
                #pragma unroll
                for (int j = 0; j < 4; j++) {
                    float2 p = unpk(acc[i][j]);
                    if (p.x >= thr) {
                        int pos = atomicAdd(&s_cnt[row], 1);
                        if (pos < CAND_CAP) s_cand[row * CAND_CAP + pos] = code0 + tx * 8 + 2 * j;
                    }
                    if (p.y >= thr) {
                        int pos = atomicAdd(&s_cnt[row], 1);
                        if (pos < CAND_CAP) s_cand[row * CAND_CAP + pos] = code0 + tx * 8 + 2 * j + 1;
                    }
                }
            }
        }
    }

    __syncthreads();
    if (t < MT) {
        int n = n0 + t;
        g_bi[n] = s_bi[t];
        g_bd[n] = s_bv[t];
        int cnt = s_cnt[t];
        g_ncand[n] = cnt;
        int m = cnt < CAND_CAP ? cnt : CAND_CAP;
        for (int c = 0; c < m; c++) g_cand[n * CAND_CAP + c] = s_cand[t * CAND_CAP + c];
    }
    CP_WAIT_0();
    #undef KICK_TILE
}

// ---------------------------------------------------------------------------
// Kernel 3: exact re-ranking (fp64), emulating reference arithmetic.
// ---------------------------------------------------------------------------
__global__ void k_refine(float* __restrict__ out_idx) {
    int warp = (blockIdx.x * blockDim.x + threadIdx.x) >> 5;
    int lane = threadIdx.x & 31;
    __shared__ double s_loss;
    if (threadIdx.x == 0) s_loss = 0.0;
    __syncthreads();

    if (warp < NQ) {
        int n = warp;
        int cnt = g_ncand[n];
        int bi; float bd;
        if (cnt <= 1) {
            bi = g_bi[n]; bd = g_bd[n];
        } else {
            float zr[8];
            #pragma unroll
            for (int m = 0; m < 8; m++) zr[m] = g_zf[(long)n * CDIM + lane + 32 * m];
            double z2 = 0.0;
            #pragma unroll
            for (int m = 0; m < 8; m++) z2 += (double)zr[m] * (double)zr[m];
            #pragma unroll
            for (int off = 16; off > 0; off >>= 1)
                z2 += __shfl_xor_sync(0xFFFFFFFFu, z2, off);
            float zf2f = (float)z2;

            bool overflow = (cnt > CAND_CAP);
            int ncand = overflow ? KCODES : cnt;
            float dmin = 3.4e38f; int kmin = 0x7FFFFFFF; float bestdot = 0.0f;
            for (int ci = 0; ci < ncand; ci++) {
                int k = overflow ? ci : g_cand[n * CAND_CAP + ci];
                double dot = 0.0;
                const float* wrow = g_wn + (long)k * CDIM;
                #pragma unroll
                for (int m = 0; m < 8; m++)
                    dot += (double)zr[m] * (double)wrow[lane + 32 * m];
                #pragma unroll
                for (int off = 16; off > 0; off >>= 1)
                    dot += __shfl_xor_sync(0xFFFFFFFFu, dot, off);
                float dotf = (float)dot;
                float d = (zf2f + g_wn2[k]) - 2.0f * dotf;
                if (d < dmin || (d == dmin && k < kmin)) { dmin = d; kmin = k; bestdot = dotf; }
            }
            bi = kmin; bd = bestdot;
        }
        if (lane == 0) {
            g_bi[n] = bi;
            out_idx[n] = (float)bi;
            atomicAdd(&s_loss, (double)g_en2[bi] - 2.0 * (double)bd * (double)g_en[bi]);
        }
    }
    __syncthreads();
    if (threadIdx.x == 0) atomicAdd(&g_loss, s_loss);
}

// ---------------------------------------------------------------------------
// Kernel 4: direct gather (proven: 75us profiled)
// ---------------------------------------------------------------------------
__global__ void k_gather(const float* __restrict__ emb, float* __restrict__ out) {
    int tid = blockIdx.x * blockDim.x + threadIdx.x;
    const int stride = gridDim.x * blockDim.x;
    #pragma unroll 4
    for (int idx = tid; idx < ZQ_ELEMS; idx += stride) {
        int w = idx & 63;
        int h = (idx >> 6) & 63;
        int c = (idx >> 12) & 255;
        int b = idx >> 20;
        int n = (b << 12) | (h << 6) | w;
        out[idx] = __ldg(&emb[(size_t)g_bi[n] * CDIM + c]);
    }
}

// ---------------------------------------------------------------------------
// Kernel 5: finalize loss. Sum_n ||zf_n||^2 == 262144 exactly.
// ---------------------------------------------------------------------------
__global__ void k_loss(float* __restrict__ out_loss) {
    double S = g_loss + 262144.0;
    out_loss[0] = (float)(1.25 * S / (double)ZQ_ELEMS);
}

// ---------------------------------------------------------------------------
extern "C" void kernel_launch(void* const* d_in, const int* in_sizes, int n_in,
                              void* d_out, int out_size) {
    const float* z   = (const float*)d_in[0];
    const float* emb = (const float*)d_in[1];
    float* out = (float*)d_out;

    cudaFuncSetAttribute(k_gemm_argmax, cudaFuncAttributeMaxDynamicSharedMemorySize, SM_TOTAL);

    k_prepnorm<<<2048, 256>>>(z, emb);                 // 1
    k_marker<<<1, 32>>>();                             // 2
    k_marker<<<1, 32>>>();                             // 3
    k_gemm_argmax<<<NQ / MT, 256, SM_TOTAL>>>();       // 4  <- profiled
    k_refine<<<NQ / 8, 256>>>(out + ZQ_ELEMS);         // 5
    k_gather<<<2048, 256>>>(emb, out);                 // 6
    k_loss<<<1, 1>>>(out + ZQ_ELEMS + NQ);             // 7
}

// round 16
// speedup vs baseline: 1.2238x; 1.0978x over previous
#include <cuda_runtime.h>
#include <math.h>
#include <stdint.h>

// Problem constants
#define BQ   16
#define CDIM 256
#define HW   64
#define NQ   65536
#define KCODES 1024
#define ZQ_ELEMS 16777216

#define MARGIN 1e-3f
#define CAND_CAP 8

// GEMM tiling (KT=32 proven best: 728us profiled)
#define MT   128
#define NTC  128
#define KT   32
#define NCHUNKS 8
#define KTILES  8
#define NTILES  (NCHUNKS * KTILES)       // 64

typedef unsigned long long u64;

// Dynamic smem (bytes): A[3][32][128]f, B[3][32][128]f, epilogue arrays
#define SMA_OFF   0                      // 3 * 16384
#define SMB_OFF   49152                  // 3 * 16384
#define SBV_OFF   98304
#define SBI_OFF   (SBV_OFF + 512)
#define SCNT_OFF  (SBI_OFF + 512)
#define SCAND_OFF (SCNT_OFF + 512)
#define SM_TOTAL  (SCAND_OFF + MT * CAND_CAP * 4)   // 103936

// Scratch
__device__ float  g_zfT[(size_t)CDIM * NQ];  // [C][N] (GEMM A + refine, strided)
__device__ float  g_wn [KCODES * CDIM];      // [K][C] (refine)
__device__ float  g_wnT[CDIM * KCODES];      // [C][K] (GEMM B)
__device__ float  g_wn2[KCODES];
__device__ float  g_en [KCODES];
__device__ float  g_en2[KCODES];
__device__ int    g_bi[NQ];
__device__ float  g_bd[NQ];
__device__ int    g_ncand[NQ];
__device__ int    g_cand[NQ * CAND_CAP];
__device__ double g_loss;
__device__ unsigned int g_ticket;

// ---- helpers ----
__device__ __forceinline__ uint32_t smem_u32(const void* p) {
    uint32_t a;
    asm("{ .reg .u64 t; cvta.to.shared.u64 t, %1; cvt.u32.u64 %0, t; }" : "=r"(a) : "l"(p));
    return a;
}
__device__ __forceinline__ u64 pack_dup(float a) {
    u64 r; asm("mov.b64 %0, {%1, %1};" : "=l"(r) : "f"(a)); return r;
}
__device__ __forceinline__ void ffma2(u64& d, u64 a, u64 b) {
    asm("fma.rn.f32x2 %0, %1, %2, %0;" : "+l"(d) : "l"(a), "l"(b));
}
__device__ __forceinline__ float2 unpk(u64 v) {
    float2 f; asm("mov.b64 {%0, %1}, %2;" : "=f"(f.x), "=f"(f.y) : "l"(v)); return f;
}
__device__ __forceinline__ void cpasync16(uint32_t dst, const void* src) {
    asm volatile("cp.async.cg.shared.global [%0], [%1], 16;" :: "r"(dst), "l"(src));
}
#define CP_COMMIT() asm volatile("cp.async.commit_group;" ::: "memory")
#define CP_WAIT_1() asm volatile("cp.async.wait_group 1;" ::: "memory")
#define CP_WAIT_0() asm volatile("cp.async.wait_group 0;" ::: "memory")

// Markstein correctly-rounded fp32 division (bit-equal to '/')
__device__ __forceinline__ float div_rn(float x, float d, float r) {
    float q = x * r;
    return fmaf(fmaf(-q, d, x), r, q);
}

// ---------------------------------------------------------------------------
// Launch 1: normalize embedding rows (ref-emulating), norms, transposed copy,
// reset per-call accumulators.
// ---------------------------------------------------------------------------
__global__ void k_prep(const float* __restrict__ emb) {
    int k = blockIdx.x, t = threadIdx.x;
    if (k == 0 && t == 0) { g_loss = 0.0; g_ticket = 0u; }

    __shared__ double red[256];
    float v = emb[k * CDIM + t];
    red[t] = (double)v * (double)v;
    __syncthreads();
    #pragma unroll
    for (int s = 128; s > 0; s >>= 1) { if (t < s) red[t] += red[t + s]; __syncthreads(); }
    __shared__ float sDen;
    if (t == 0) {
        float n2 = (float)red[0];
        float n  = sqrtf(n2);
        float dd = fmaxf(n, 1e-12f);
        g_en[k] = dd; g_en2[k] = n2; sDen = dd;
    }
    __syncthreads();
    float wn = v / sDen;
    g_wn [k * CDIM + t]   = wn;
    g_wnT[t * KCODES + k] = wn;

    red[t] = (double)wn * (double)wn;
    __syncthreads();
    #pragma unroll
    for (int s = 128; s > 0; s >>= 1) { if (t < s) red[t] += red[t + s]; __syncthreads(); }
    if (t == 0) g_wn2[k] = (float)red[0];
}

// ---------------------------------------------------------------------------
// Launch 2: GEMM screen with fused znorm prologue.
// Each CTA first normalizes ITS OWN 128 queries (2 (b,h) pairs x 256 channels,
// warp-per-row, fp64 sumsq, one division + Markstein = bit-equal to '/'),
// writing its exclusive g_zfT column slice. Then the proven KT=32 fp32x2
// pipelined GEMM + argmax + margin-candidate collection.
// ---------------------------------------------------------------------------
__global__ void __launch_bounds__(256, 2) k_gemm_argmax(const float* __restrict__ z) {
    extern __shared__ float smem[];
    float* s_bv   = smem + SBV_OFF / 4;
    int*   s_bi   = (int*)(smem + SBI_OFF / 4);
    int*   s_cnt  = (int*)(smem + SCNT_OFF / 4);
    int*   s_cand = (int*)(smem + SCAND_OFF / 4);

    const int t  = threadIdx.x;
    const int tx = t & 15;
    const int ty = t >> 4;
    const int n0 = blockIdx.x * MT;

    // ===== znorm prologue: 512 rows = 2 (b,h) pairs x 256 channels =====
    {
        const int warp = t >> 5, lane = t & 31;
        #pragma unroll 1
        for (int i = 0; i < 64; i++) {
            int rr   = warp * 64 + i;             // 0..511
            int pair = rr >> 8;                   // 0/1
            int c    = rr & 255;
            int bh   = blockIdx.x * 2 + pair;
            int b    = bh >> 6, h = bh & 63;
            const float* src = z + (((size_t)b * CDIM + c) * HW + h) * HW;
            float v0 = src[lane];
            float v1 = src[lane + 32];
            double s = (double)v0 * v0 + (double)v1 * v1;
            #pragma unroll
            for (int off = 16; off > 0; off >>= 1)
                s += __shfl_xor_sync(0xFFFFFFFFu, s, off);
            float den = fmaxf(sqrtf((float)s), 1e-12f);
            float r0 = 0.0f;
            if (lane == 0) r0 = 1.0f / den;       // one true division per row
            float r = __shfl_sync(0xFFFFFFFFu, r0, 0);
            float* dst = g_zfT + (size_t)c * NQ + (size_t)bh * 64;
            dst[lane]      = div_rn(v0, den, r);
            dst[lane + 32] = div_rn(v1, den, r);
        }
    }
    __threadfence_block();
    __syncthreads();

    if (t < MT) { s_bv[t] = -3.0e38f; s_bi[t] = 0; s_cnt[t] = 0; }

    const uint32_t smb = smem_u32(smem);
    const int lr = t >> 5;
    const int lc = (t & 31) * 16;

    #define KICK_TILE(bt_) do {                                                   \
        const int ch_ = (bt_) >> 3, kt_ = (bt_) & 7;                              \
        const int buf_ = (bt_) % 3;                                               \
        const uint32_t ab = smb + (uint32_t)(SMA_OFF + buf_ * 16384);             \
        const uint32_t bb = smb + (uint32_t)(SMB_OFF + buf_ * 16384);             \
        _Pragma("unroll")                                                         \
        for (int i_ = 0; i_ < 4; i_++) {                                          \
            int r_ = lr + i_ * 8;                                                 \
            cpasync16(ab + (uint32_t)(r_ * 512 + lc),                             \
                      g_zfT + (size_t)(kt_ * KT + r_) * NQ + n0 + (lc >> 2));     \
            cpasync16(bb + (uint32_t)(r_ * 512 + lc),                             \
                      g_wnT + (size_t)(kt_ * KT + r_) * KCODES + ch_ * NTC        \
                            + (lc >> 2));                                         \
        }                                                                         \
    } while (0)

    KICK_TILE(0); CP_COMMIT();
    KICK_TILE(1); CP_COMMIT();

    u64 acc[8][4];

    for (int bt = 0; bt < NTILES; bt++) {
        CP_WAIT_1();
        __syncthreads();

        if (bt + 2 < NTILES) { KICK_TILE(bt + 2); }
        CP_COMMIT();

        const int kt  = bt & 7;
        const int buf = bt % 3;
        const float* Ab = smem + (SMA_OFF / 4) + buf * 4096;
        const float* Bb = smem + (SMB_OFF / 4) + buf * 4096;

        if (kt == 0) {
            #pragma unroll
            for (int i = 0; i < 8; i++)
                #pragma unroll
                for (int j = 0; j < 4; j++) acc[i][j] = 0ull;
        }

        #pragma unroll
        for (int kk = 0; kk < KT; kk++) {
            const float* Ak = Ab + kk * MT;
            const float* Bk = Bb + kk * NTC;
            u64 b2[4];
            #pragma unroll
            for (int j = 0; j < 4; j++)
                b2[j] = *(const u64*)(Bk + tx * 8 + 2 * j);
            float4 av0 = *(const float4*)(Ak + ty * 8);
            float4 av1 = *(const float4*)(Ak + ty * 8 + 4);
            float av[8] = {av0.x, av0.y, av0.z, av0.w, av1.x, av1.y, av1.z, av1.w};
            #pragma unroll
            for (int i = 0; i < 8; i++) {
                u64 a2 = pack_dup(av[i]);
                #pragma unroll
                for (int j = 0; j < 4; j++)
                    ffma2(acc[i][j], a2, b2[j]);
            }
        }

        if (kt == 7) {
            const int code0 = (bt >> 3) * NTC;
            #pragma unroll
            for (int i = 0; i < 8; i++) {
                float bv = -3.0e38f;
                int   bj = 0;
                #pragma unroll
                for (int j = 0; j < 4; j++) {
                    float2 p = unpk(acc[i][j]);
                    if (p.x > bv) { bv = p.x; bj = 2 * j; }
                    if (p.y > bv) { bv = p.y; bj = 2 * j + 1; }
                }
                int bc = code0 + tx * 8 + bj;
                #pragma unroll
                for (int off = 8; off > 0; off >>= 1) {
                    float ov = __shfl_xor_sync(0xFFFFFFFFu, bv, off, 16);
                    int   oc = __shfl_xor_sync(0xFFFFFFFFu, bc, off, 16);
                    if (ov > bv || (ov == bv && oc < bc)) { bv = ov; bc = oc; }
                }
                if (tx == 0) {
                    int row = ty * 8 + i;
                    if (bv > s_bv[row]) { s_bv[row] = bv; s_bi[row] = bc; }
                }
            }
            #pragma unroll
            for (int i = 0; i < 8; i++) {
                int row = ty * 8 + i;
                float thr = s_bv[row] - MARGIN;
                #pragma unroll
                for (int j = 0; j < 4; j++) {
                    float2 p = unpk(acc[i][j]);
                    if (p.x >= thr) {
                        int pos = atomicAdd(&s_cnt[row], 1);
                        if (pos < CAND_CAP) s_cand[row * CAND_CAP + pos] = code0 + tx * 8 + 2 * j;
                    }
                    if (p.y >= thr) {
                        int pos = atomicAdd(&s_cnt[row], 1);
                        if (pos < CAND_CAP) s_cand[row * CAND_CAP + pos] = code0 + tx * 8 + 2 * j + 1;
                    }
                }
            }
        }
    }

    __syncthreads();
    if (t < MT) {
        int n = n0 + t;
        g_bi[n] = s_bi[t];
        g_bd[n] = s_bv[t];
        int cnt = s_cnt[t];
        g_ncand[n] = cnt;
        int m = cnt < CAND_CAP ? cnt : CAND_CAP;
        for (int c = 0; c < m; c++) g_cand[n * CAND_CAP + c] = s_cand[t * CAND_CAP + c];
    }
    CP_WAIT_0();
    #undef KICK_TILE
}

// ---------------------------------------------------------------------------
// Launch 3: fused refine (fp64 exact re-rank) + gather + loss finalize.
// 1024 blocks x 256 threads; block bh owns queries n0=bh*64..+63 = one (b,h).
// ---------------------------------------------------------------------------
__global__ void k_finish(const float* __restrict__ emb,
                         float* __restrict__ out,
                         float* __restrict__ out_idx,
                         float* __restrict__ out_loss) {
    __shared__ int    sIdx[64];
    __shared__ double s_loss;
    const int t = threadIdx.x;
    const int warp = t >> 5, lane = t & 31;
    const int bh = blockIdx.x;
    const int b = bh >> 6, h = bh & 63;
    const int n0 = bh * 64;

    if (t == 0) s_loss = 0.0;
    __syncthreads();

    // ---- Phase 1: refine (8 queries per warp) ----
    for (int i = 0; i < 8; i++) {
        int lq = warp * 8 + i;
        int n  = n0 + lq;
        int cnt = g_ncand[n];
        int bi; float bd;
        if (cnt <= 1) {
            bi = g_bi[n]; bd = g_bd[n];
        } else {
            float zr[8];
            #pragma unroll
            for (int m = 0; m < 8; m++)
                zr[m] = g_zfT[(size_t)(lane + 32 * m) * NQ + n];
            double z2 = 0.0;
            #pragma unroll
            for (int m = 0; m < 8; m++) z2 += (double)zr[m] * (double)zr[m];
            #pragma unroll
            for (int off = 16; off > 0; off >>= 1)
                z2 += __shfl_xor_sync(0xFFFFFFFFu, z2, off);
            float zf2f = (float)z2;

            bool overflow = (cnt > CAND_CAP);
            int ncand = overflow ? KCODES : cnt;
            float dmin = 3.4e38f; int kmin = 0x7FFFFFFF; float bestdot = 0.0f;
            for (int ci = 0; ci < ncand; ci++) {
                int k = overflow ? ci : g_cand[n * CAND_CAP + ci];
                double dot = 0.0;
                const float* wrow = g_wn + (size_t)k * CDIM;
                #pragma unroll
                for (int m = 0; m < 8; m++)
                    dot += (double)zr[m] * (double)wrow[lane + 32 * m];
                #pragma unroll
                for (int off = 16; off > 0; off >>= 1)
                    dot += __shfl_xor_sync(0xFFFFFFFFu, dot, off);
                float dotf = (float)dot;
                float d = (zf2f + g_wn2[k]) - 2.0f * dotf;
                if (d < dmin || (d == dmin && k < kmin)) { dmin = d; kmin = k; bestdot = dotf; }
            }
            bi = kmin; bd = bestdot;
        }
        if (lane == 0) {
            sIdx[lq] = bi;
            out_idx[n] = (float)bi;
            atomicAdd(&s_loss, (double)g_en2[bi] - 2.0 * (double)bd * (double)g_en[bi]);
        }
    }
    __syncthreads();

    // ---- Phase 2: gather-write this (b,h)'s output tile [256 c x 64 w] ----
    for (int i = t; i < CDIM * 64; i += 256) {
        int c = i >> 6, w = i & 63;
        out[(((size_t)b * CDIM + c) * HW + h) * HW + w] =
            __ldg(&emb[(size_t)sIdx[w] * CDIM + c]);
    }

    // ---- Phase 3: loss accumulate + last-block finalize ----
    __syncthreads();
    if (t == 0) {
        atomicAdd(&g_loss, s_loss);
        __threadfence();
        unsigned int old = atomicInc(&g_ticket, 0xFFFFFFFFu);
        if (old == (unsigned int)(gridDim.x - 1)) {
            double S = atomicAdd(&g_loss, 0.0) + 262144.0;
            out_loss[0] = (float)(1.25 * S / (double)ZQ_ELEMS);
        }
    }
}

// ---------------------------------------------------------------------------
extern "C" void kernel_launch(void* const* d_in, const int* in_sizes, int n_in,
                              void* d_out, int out_size) {
    const float* z   = (const float*)d_in[0];
    const float* emb = (const float*)d_in[1];
    float* out = (float*)d_out;

    cudaFuncSetAttribute(k_gemm_argmax, cudaFuncAttributeMaxDynamicSharedMemorySize, SM_TOTAL);

    k_prep<<<KCODES, 256>>>(emb);                          // 1
    k_gemm_argmax<<<NQ / MT, 256, SM_TOTAL>>>(z);          // 2 (znorm fused)
    k_finish<<<BQ * HW, 256>>>(emb, out,
                               out + ZQ_ELEMS,
                               out + ZQ_ELEMS + NQ);       // 3 (refine+gather+loss)
}

// round 17
// speedup vs baseline: 3.1365x; 2.5630x over previous
#include <cuda_runtime.h>
#include <math.h>
#include <stdint.h>

// Problem constants
#define BQ   16
#define CDIM 256
#define HW   64
#define NQ   65536
#define KCODES 1024
#define ZQ_ELEMS 16777216

#define MARGIN 1e-3f
#define UCAP 4                 // candidates kept per (unit,row)

// GEMM tiling: unit = 128 queries x 128 codes, K=256 as 8 tiles of 32
#define MT   128
#define NTC  128
#define KT   32
#define NUNITS 4096            // 512 qblocks * 8 chunks
#define PERSIST_CTAS 296       // 148 SMs * 2 CTAs

typedef unsigned long long u64;

// Dynamic smem (bytes): A[3][32][128]f + B[3][32][128]f
#define SMA_OFF   0
#define SMB_OFF   49152
#define SM_TOTAL  98304

// Scratch
__device__ float  g_zfT[(size_t)CDIM * NQ];  // [C][N] normalized queries
__device__ float  g_wn [KCODES * CDIM];      // [K][C] (refine)
__device__ float  g_wnT[CDIM * KCODES];      // [C][K] (GEMM B)
__device__ float  g_wn2[KCODES];
__device__ float  g_en [KCODES];
__device__ float  g_en2[KCODES];
__device__ float  g_ubv[NUNITS * 128];       // per-unit best value
__device__ int    g_ubi[NUNITS * 128];       // per-unit best index
__device__ int    g_ucnt[NUNITS * 128];      // per-unit candidate count
__device__ int    g_ucand[NUNITS * 128 * UCAP];
__device__ double g_loss;
__device__ unsigned int g_ticket;            // finish loss ticket
__device__ unsigned int g_unit;              // gemm work ticket

// ---- helpers ----
__device__ __forceinline__ uint32_t smem_u32(const void* p) {
    uint32_t a;
    asm("{ .reg .u64 t; cvta.to.shared.u64 t, %1; cvt.u32.u64 %0, t; }" : "=r"(a) : "l"(p));
    return a;
}
__device__ __forceinline__ u64 pack_dup(float a) {
    u64 r; asm("mov.b64 %0, {%1, %1};" : "=l"(r) : "f"(a)); return r;
}
__device__ __forceinline__ void ffma2(u64& d, u64 a, u64 b) {
    asm("fma.rn.f32x2 %0, %1, %2, %0;" : "+l"(d) : "l"(a), "l"(b));
}
__device__ __forceinline__ float2 unpk(u64 v) {
    float2 f; asm("mov.b64 {%0, %1}, %2;" : "=f"(f.x), "=f"(f.y) : "l"(v)); return f;
}
__device__ __forceinline__ void cpasync16(uint32_t dst, const void* src) {
    asm volatile("cp.async.cg.shared.global [%0], [%1], 16;" :: "r"(dst), "l"(src));
}
#define CP_COMMIT() asm volatile("cp.async.commit_group;" ::: "memory")
#define CP_WAIT_1() asm volatile("cp.async.wait_group 1;" ::: "memory")
#define CP_WAIT_0() asm volatile("cp.async.wait_group 0;" ::: "memory")

// Markstein correctly-rounded fp32 division (bit-equal to '/')
__device__ __forceinline__ float div_rn(float x, float d, float r) {
    float q = x * r;
    return fmaf(fmaf(-q, d, x), r, q);
}

// ---------------------------------------------------------------------------
// Launch 1: fused prep (blocks 1024..2047) + znorm (blocks 0..1023)
// ---------------------------------------------------------------------------
__global__ void k_prepnorm(const float* __restrict__ z, const float* __restrict__ emb) {
    __shared__ float tile[64][65];
    __shared__ float den[64];
    __shared__ float rcp[64];
    __shared__ double red[256];

    const int t = threadIdx.x;

    if (blockIdx.x >= 1024) {
        int k = blockIdx.x - 1024;
        if (k == 0 && t == 0) { g_loss = 0.0; g_ticket = 0u; g_unit = 0u; }

        float v = emb[k * CDIM + t];
        red[t] = (double)v * (double)v;
        __syncthreads();
        #pragma unroll
        for (int s = 128; s > 0; s >>= 1) { if (t < s) red[t] += red[t + s]; __syncthreads(); }
        __shared__ float sDen;
        if (t == 0) {
            float n2 = (float)red[0];
            float n  = sqrtf(n2);
            float dd = fmaxf(n, 1e-12f);
            g_en[k] = dd; g_en2[k] = n2; sDen = dd;
        }
        __syncthreads();
        float wn = v / sDen;
        g_wn [k * CDIM + t]   = wn;
        g_wnT[t * KCODES + k] = wn;

        red[t] = (double)wn * (double)wn;
        __syncthreads();
        #pragma unroll
        for (int s = 128; s > 0; s >>= 1) { if (t < s) red[t] += red[t + s]; __syncthreads(); }
        if (t == 0) g_wn2[k] = (float)red[0];
        return;
    }

    int bh = blockIdx.x;
    int b = bh >> 6, h = bh & 63;
    long n0 = (long)bh * 64;

    for (int c0 = 0; c0 < CDIM; c0 += 64) {
        for (int i = t; i < 4096; i += 256) {
            int r = i >> 6, w = i & 63;
            tile[r][w] = z[(((long)b * CDIM + (c0 + r)) * HW + h) * HW + w];
        }
        __syncthreads();
        if (t < 64) {
            double s = 0.0;
            #pragma unroll
            for (int w = 0; w < 64; w++) { double v = (double)tile[t][w]; s += v * v; }
            float d = fmaxf(sqrtf((float)s), 1e-12f);
            den[t] = d;
            rcp[t] = 1.0f / d;
        }
        __syncthreads();
        // write normalized, transposed to zfT [C][N] (coalesced in w)
        for (int i = t; i < 4096; i += 256) {
            int cc = i >> 6, w = i & 63;
            g_zfT[(long)(c0 + cc) * NQ + n0 + w] = div_rn(tile[cc][w], den[cc], rcp[cc]);
        }
        __syncthreads();
    }
}

// ---------------------------------------------------------------------------
// Launch 2: persistent fp32x2 GEMM screen. 296 CTAs, atomic ticket over
// 4096 units (qblock x chunk). Per unit: 8 k-tiles of 32 (3-stage cp.async),
// per-row best (all 16 tx-lanes via shfl) + margin candidates to gmem.
// ---------------------------------------------------------------------------
__global__ void __launch_bounds__(256, 2) k_gemm() {
    extern __shared__ float smem[];
    __shared__ int s_cnt[128];
    __shared__ unsigned int s_u;

    const int t  = threadIdx.x;
    const int tx = t & 15;
    const int ty = t >> 4;
    const uint32_t smb = smem_u32(smem);
    const int lr = t >> 5;
    const int lc = (t & 31) * 16;

    while (true) {
        if (t == 0) s_u = atomicAdd(&g_unit, 1u);
        if (t < 128) s_cnt[t] = 0;
        __syncthreads();
        const unsigned int u = s_u;
        if (u >= NUNITS) break;
        const int qb = u >> 3, ch = u & 7;
        const int n0 = qb * MT, code0 = ch * NTC;

        #define KICK_TILE(kt_) do {                                                \
            const int buf_ = (kt_) % 3;                                            \
            const uint32_t ab = smb + (uint32_t)(SMA_OFF + buf_ * 16384);          \
            const uint32_t bb = smb + (uint32_t)(SMB_OFF + buf_ * 16384);          \
            _Pragma("unroll")                                                      \
            for (int i_ = 0; i_ < 4; i_++) {                                       \
                int r_ = lr + i_ * 8;                                              \
                cpasync16(ab + (uint32_t)(r_ * 512 + lc),                          \
                          g_zfT + (size_t)((kt_) * KT + r_) * NQ + n0 + (lc >> 2));\
                cpasync16(bb + (uint32_t)(r_ * 512 + lc),                          \
                          g_wnT + (size_t)((kt_) * KT + r_) * KCODES + code0       \
                                + (lc >> 2));                                      \
            }                                                                      \
        } while (0)

        KICK_TILE(0); CP_COMMIT();
        KICK_TILE(1); CP_COMMIT();

        u64 acc[8][4];
        #pragma unroll
        for (int i = 0; i < 8; i++)
            #pragma unroll
            for (int j = 0; j < 4; j++) acc[i][j] = 0ull;

        for (int kt = 0; kt < 8; kt++) {
            CP_WAIT_1();
            __syncthreads();
            if (kt + 2 < 8) { KICK_TILE(kt + 2); }
            CP_COMMIT();

            const int buf = kt % 3;
            const float* Ab = smem + (SMA_OFF / 4) + buf * 4096;
            const float* Bb = smem + (SMB_OFF / 4) + buf * 4096;

            #pragma unroll
            for (int kk = 0; kk < KT; kk++) {
                const float* Ak = Ab + kk * MT;
                const float* Bk = Bb + kk * NTC;
                const ulonglong2* B2 = (const ulonglong2*)(Bk + tx * 8);
                ulonglong2 p0 = B2[0], p1 = B2[1];
                u64 b2[4] = {p0.x, p0.y, p1.x, p1.y};
                float4 av0 = *(const float4*)(Ak + ty * 8);
                float4 av1 = *(const float4*)(Ak + ty * 8 + 4);
                float av[8] = {av0.x, av0.y, av0.z, av0.w, av1.x, av1.y, av1.z, av1.w};
                #pragma unroll
                for (int i = 0; i < 8; i++) {
                    u64 a2 = pack_dup(av[i]);
                    #pragma unroll
                    for (int j = 0; j < 4; j++)
                        ffma2(acc[i][j], a2, b2[j]);
                }
            }
        }
        CP_WAIT_0();

        // ---- per-unit epilogue ----
        const size_t ub = (size_t)u * 128;
        #pragma unroll
        for (int i = 0; i < 8; i++) {
            const int row = ty * 8 + i;
            float bv = -3.0e38f;
            int   bj = 0;
            #pragma unroll
            for (int j = 0; j < 4; j++) {
                float2 p = unpk(acc[i][j]);
                if (p.x > bv) { bv = p.x; bj = 2 * j; }
                if (p.y > bv) { bv = p.y; bj = 2 * j + 1; }
            }
            int bc = code0 + tx * 8 + bj;
            #pragma unroll
            for (int off = 8; off > 0; off >>= 1) {
                float ov = __shfl_xor_sync(0xFFFFFFFFu, bv, off, 16);
                int   oc = __shfl_xor_sync(0xFFFFFFFFu, bc, off, 16);
                if (ov > bv || (ov == bv && oc < bc)) { bv = ov; bc = oc; }
            }
            // all 16 lanes now hold (bv,bc) for this row
            const float thr = bv - MARGIN;
            #pragma unroll
            for (int j = 0; j < 4; j++) {
                float2 p = unpk(acc[i][j]);
                if (p.x >= thr) {
                    int pos = atomicAdd(&s_cnt[row], 1);
                    if (pos < UCAP) g_ucand[(ub + row) * UCAP + pos] = code0 + tx * 8 + 2 * j;
                }
                if (p.y >= thr) {
                    int pos = atomicAdd(&s_cnt[row], 1);
                    if (pos < UCAP) g_ucand[(ub + row) * UCAP + pos] = code0 + tx * 8 + 2 * j + 1;
                }
            }
            if (tx == 0) { g_ubv[ub + row] = bv; g_ubi[ub + row] = bc; }
        }
        __syncthreads();
        if (t < 128) g_ucnt[ub + t] = s_cnt[t];
        #undef KICK_TILE
    }
}

// ---------------------------------------------------------------------------
// Launch 3: merge unit partials + fp64 exact refine + gather + loss.
// 1024 blocks x 256 threads; block bh owns queries bh*64..+63 = one (b,h).
// ---------------------------------------------------------------------------
__global__ void k_finish(const float* __restrict__ emb,
                         float* __restrict__ out,
                         float* __restrict__ out_idx,
                         float* __restrict__ out_loss) {
    __shared__ int    sIdx[64];
    __shared__ double s_loss;
    __shared__ int    s_list[64][40];
    __shared__ int    s_ln[64];
    const int t = threadIdx.x;
    const int warp = t >> 5, lane = t & 31;
    const int bh = blockIdx.x;
    const int b = bh >> 6, h = bh & 63;
    const int n0 = bh * 64;

    if (t == 0) s_loss = 0.0;
    __syncthreads();

    for (int i = 0; i < 8; i++) {
        const int lq = warp * 8 + i;
        const int n  = n0 + lq;
        const int qb = n >> 7, row = n & 127;
        const size_t base0 = ((size_t)qb * 8) * 128 + row;   // + ch*128

        // merge 8 unit bests (lanes 0..7)
        float bv = (lane < 8) ? g_ubv[base0 + (size_t)lane * 128] : -3.0e38f;
        int   bi = (lane < 8) ? g_ubi[base0 + (size_t)lane * 128] : 0x7FFFFFFF;
        #pragma unroll
        for (int off = 4; off > 0; off >>= 1) {
            float ov = __shfl_xor_sync(0xFFFFFFFFu, bv, off);
            int   oi = __shfl_xor_sync(0xFFFFFFFFu, bi, off);
            if (ov > bv || (ov == bv && oi < bi)) { bv = ov; bi = oi; }
        }
        bv = __shfl_sync(0xFFFFFFFFu, bv, 0);
        bi = __shfl_sync(0xFFFFFFFFu, bi, 0);
        const float thr = bv - MARGIN;

        // build candidate list (lane 0)
        if (lane == 0) {
            int ln = 0;
            for (int ch = 0; ch < 8; ch++) {
                size_t p = base0 + (size_t)ch * 128;
                if (g_ubv[p] >= thr) {
                    int c = g_ucnt[p];
                    if (c > UCAP) {
                        s_list[lq][ln++] = -(ch + 1);       // overflow: rescan chunk
                    } else {
                        for (int j = 0; j < c; j++)
                            s_list[lq][ln++] = g_ucand[p * UCAP + j];
                    }
                }
            }
            s_ln[lq] = ln;
        }
        __syncwarp();
        const int ln = s_ln[lq];

        int   fbi; float fbd;
        if (ln == 1 && s_list[lq][0] == bi) {
            fbi = bi; fbd = bv;                              // unambiguous screen winner
        } else {
            // fp64 exact re-rank over the list (markers expand to whole chunk)
            float zr[8];
            #pragma unroll
            for (int m = 0; m < 8; m++)
                zr[m] = g_zfT[(size_t)(lane + 32 * m) * NQ + n];
            double z2 = 0.0;
            #pragma unroll
            for (int m = 0; m < 8; m++) z2 += (double)zr[m] * (double)zr[m];
            #pragma unroll
            for (int off = 16; off > 0; off >>= 1)
                z2 += __shfl_xor_sync(0xFFFFFFFFu, z2, off);
            const float zf2f = (float)z2;

            float dmin = 3.4e38f; int kmin = 0x7FFFFFFF; float bestdot = 0.0f;
            for (int e = 0; e < ln; e++) {
                int entry = s_list[lq][e];
                int kfirst = entry, kcount = 1;
                if (entry < 0) { kfirst = (-entry - 1) * NTC; kcount = NTC; }
                for (int kc = 0; kc < kcount; kc++) {
                    int k = kfirst + kc;
                    double dot = 0.0;
                    const float* wrow = g_wn + (size_t)k * CDIM;
                    #pragma unroll
                    for (int m = 0; m < 8; m++)
                        dot += (double)zr[m] * (double)wrow[lane + 32 * m];
                    #pragma unroll
                    for (int off = 16; off > 0; off >>= 1)
                        dot += __shfl_xor_sync(0xFFFFFFFFu, dot, off);
                    float dotf = (float)dot;
                    float d = (zf2f + g_wn2[k]) - 2.0f * dotf;
                    if (d < dmin || (d == dmin && k < kmin)) { dmin = d; kmin = k; bestdot = dotf; }
                }
            }
            fbi = kmin; fbd = bestdot;
        }
        if (lane == 0) {
            sIdx[lq] = fbi;
            out_idx[n] = (float)fbi;
            atomicAdd(&s_loss, (double)g_en2[fbi] - 2.0 * (double)fbd * (double)g_en[fbi]);
        }
    }
    __syncthreads();

    // ---- gather-write this (b,h)'s output tile [256 c x 64 w] ----
    for (int i = t; i < CDIM * 64; i += 256) {
        int c = i >> 6, w = i & 63;
        out[(((size_t)b * CDIM + c) * HW + h) * HW + w] =
            __ldg(&emb[(size_t)sIdx[w] * CDIM + c]);
    }

    // ---- loss accumulate + last-block finalize ----
    __syncthreads();
    if (t == 0) {
        atomicAdd(&g_loss, s_loss);
        __threadfence();
        unsigned int old = atomicInc(&g_ticket, 0xFFFFFFFFu);
        if (old == (unsigned int)(gridDim.x - 1)) {
            double S = atomicAdd(&g_loss, 0.0) + 262144.0;
            out_loss[0] = (float)(1.25 * S / (double)ZQ_ELEMS);
        }
    }
}

// ---------------------------------------------------------------------------
extern "C" void kernel_launch(void* const* d_in, const int* in_sizes, int n_in,
                              void* d_out, int out_size) {
    const float* z   = (const float*)d_in[0];
    const float* emb = (const float*)d_in[1];
    float* out = (float*)d_out;

    cudaFuncSetAttribute(k_gemm, cudaFuncAttributeMaxDynamicSharedMemorySize, SM_TOTAL);

    k_prepnorm<<<2048, 256>>>(z, emb);                     // 1
    k_gemm<<<PERSIST_CTAS, 256, SM_TOTAL>>>();             // 2 (persistent, ticketed)
    k_finish<<<BQ * HW, 256>>>(emb, out,
                               out + ZQ_ELEMS,
                               out + ZQ_ELEMS + NQ);       // 3
}